// round 2
// baseline (speedup 1.0000x reference)
#include <cuda_runtime.h>
#include <cstdint>

#define LDA 132          // smem stride for data tiles (conflict-free A-frag loads)
#define LDW 136          // smem stride for weight tiles (conflict-free B-frag loads)
#define THREADS 256
#define SMEM_FLOATS (128*LDA*2 + 128*LDW)
#define SMEM_BYTES (SMEM_FLOATS*4)

__device__ __forceinline__ float tf32r(float v){
    uint32_t u;
    asm("cvt.rna.tf32.f32 %0, %1;" : "=r"(u) : "f"(v));
    return __uint_as_float(u);
}

__device__ __forceinline__ float sigf(float v){
    float t = __expf(-v);
    return __fdividef(1.0f, 1.0f + t);
}

__device__ __forceinline__ float tanhfast(float v){
    v = fminf(fmaxf(v, -15.0f), 15.0f);
    float t = __expf(-2.0f*v);
    return __fdividef(1.0f - t, 1.0f + t);
}

__device__ __forceinline__ void mma8(float* c, const uint32_t* a, const uint32_t* b){
    asm volatile(
      "mma.sync.aligned.m16n8k8.row.col.f32.tf32.tf32.f32 "
      "{%0,%1,%2,%3},{%4,%5,%6,%7},{%8,%9},{%0,%1,%2,%3};\n"
      : "+f"(c[0]), "+f"(c[1]), "+f"(c[2]), "+f"(c[3])
      : "r"(a[0]), "r"(a[1]), "r"(a[2]), "r"(a[3]),
        "r"(b[0]), "r"(b[1]));
}

// 128x128x128 tf32 GEMM, 8 warps arranged 2(m) x 4(n); each warp: 64 rows x 32 cols.
__device__ __forceinline__ void gemm128(float (&acc)[4][4][4],
                                        const float* __restrict__ As,
                                        const float* __restrict__ Bs,
                                        int g, int r, int wm, int wn)
{
    #pragma unroll 2
    for (int k8 = 0; k8 < 16; k8++){
        const int kk = k8*8;
        uint32_t a[4][4];
        #pragma unroll
        for (int mt=0; mt<4; mt++){
            const float* ap = As + (wm*64 + mt*16 + g)*LDA + kk + r;
            a[mt][0] = __float_as_uint(ap[0]);
            a[mt][1] = __float_as_uint(ap[8*LDA]);
            a[mt][2] = __float_as_uint(ap[4]);
            a[mt][3] = __float_as_uint(ap[8*LDA+4]);
        }
        uint32_t b[4][2];
        #pragma unroll
        for (int nt=0; nt<4; nt++){
            const float* bp = Bs + (kk + r)*LDW + wn*32 + nt*8 + g;
            b[nt][0] = __float_as_uint(bp[0]);
            b[nt][1] = __float_as_uint(bp[4*LDW]);
        }
        #pragma unroll
        for (int mt=0; mt<4; mt++)
          #pragma unroll
          for (int nt=0; nt<4; nt++)
            mma8(acc[mt][nt], a[mt], b[nt]);
    }
}

__device__ __forceinline__ void load_cvt(float* dst, int ld,
                                         const float* __restrict__ src, int rs, int tid){
    #pragma unroll
    for (int i=0;i<16;i++){
        int e = tid + i*THREADS;
        int row = e >> 5;
        int c4  = (e & 31) * 4;
        float4 v = *reinterpret_cast<const float4*>(src + row*rs + c4);
        v.x = tf32r(v.x); v.y = tf32r(v.y); v.z = tf32r(v.z); v.w = tf32r(v.w);
        *reinterpret_cast<float4*>(dst + row*ld + c4) = v;
    }
}

// Load child_h tile k into xs (tf32), and accumulate the raw fp32 values into hs.
__device__ __forceinline__ void load_child_cvt_accum(float* xs, float* hs,
        const float* __restrict__ ch, int m0, int k, int tid){
    #pragma unroll
    for (int i=0;i<16;i++){
        int e = tid + i*THREADS;
        int row = e >> 5;
        int c4  = (e & 31)*4;
        float4 v = *reinterpret_cast<const float4*>(ch + ((m0+row)*8 + k)*128 + c4);
        float4* hp = reinterpret_cast<float4*>(hs + row*LDA + c4);
        float4 h = *hp;
        h.x += v.x; h.y += v.y; h.z += v.z; h.w += v.w;
        *hp = h;
        v.x = tf32r(v.x); v.y = tf32r(v.y); v.z = tf32r(v.z); v.w = tf32r(v.w);
        *reinterpret_cast<float4*>(xs + row*LDA + c4) = v;
    }
}

#define ZERO_ACC(A) { _Pragma("unroll") for(int _m=0;_m<4;_m++) _Pragma("unroll") for(int _n=0;_n<4;_n++) _Pragma("unroll") for(int _e=0;_e<4;_e++) (A)[_m][_n][_e]=0.0f; }

__global__ void __launch_bounds__(THREADS, 1)
treelstm_kernel(const float* __restrict__ x,
                const float* __restrict__ child_h,
                const float* __restrict__ child_c,
                const float* __restrict__ Wi, const float* __restrict__ bi, const float* __restrict__ Ui,
                const float* __restrict__ Wo, const float* __restrict__ bo, const float* __restrict__ Uo,
                const float* __restrict__ Wu, const float* __restrict__ bu, const float* __restrict__ Uu,
                const float* __restrict__ Wf, const float* __restrict__ bf, const float* __restrict__ Uf,
                float* __restrict__ out, int N)
{
    extern __shared__ float smem[];
    float* xs = smem;               // 128*LDA : x tile / child_h tile (tf32)
    float* hs = xs + 128*LDA;       // 128*LDA : h_sum tile
    float* wb = hs + 128*LDA;       // 128*LDW : current weight tile (tf32)

    const int tid  = threadIdx.x;
    const int lane = tid & 31;
    const int g    = lane >> 2;     // group id (row within frag)
    const int r    = lane & 3;      // thread id in group (k/col within frag)
    const int wid  = tid >> 5;
    const int wm   = wid & 1;       // warp m-group (0..1)
    const int wn   = wid >> 1;      // warp n-group (0..3)
    const int m0   = blockIdx.x * 128;

    // zero h_sum (each thread owns a fixed set of elements; no sync needed vs. its own later adds)
    #pragma unroll
    for (int i=0;i<16;i++){
        int e = tid + i*THREADS;
        int row = e>>5, c4=(e&31)*4;
        *reinterpret_cast<float4*>(hs + row*LDA + c4) = make_float4(0.f,0.f,0.f,0.f);
    }

    float acc [4][4][4];
    float cacc[4][4][4];   // c accumulator: i*u + sum_k f_k * child_c_k
    float aux [4][4][4];   // holds xf = x@Wf+bf during child loop, later u = tanh(...)

    // ---- phase 1: xf = x @ Wf + bf -------------------------------------
    load_cvt(xs, LDA, x + m0*128, 128, tid);
    load_cvt(wb, LDW, Wf, 128, tid);
    __syncthreads();
    ZERO_ACC(acc);
    gemm128(acc, xs, wb, g, r, wm, wn);
    __syncthreads();                       // xs/wb about to be overwritten

    #pragma unroll
    for (int mt=0;mt<4;mt++)
      #pragma unroll
      for (int nt=0;nt<4;nt++){
        int C0 = wn*32 + nt*8 + 2*r;
        float2 bv = *reinterpret_cast<const float2*>(bf + C0);
        aux[mt][nt][0] = acc[mt][nt][0] + bv.x;
        aux[mt][nt][1] = acc[mt][nt][1] + bv.y;
        aux[mt][nt][2] = acc[mt][nt][2] + bv.x;
        aux[mt][nt][3] = acc[mt][nt][3] + bv.y;
        cacc[mt][nt][0]=0.f; cacc[mt][nt][1]=0.f; cacc[mt][nt][2]=0.f; cacc[mt][nt][3]=0.f;
      }

    // ---- phase 2: children: F_k = ch_k @ Uf; f=sig(xf+F_k); cacc += f*cc_k; hs += ch_k
    load_cvt(wb, LDW, Uf, 128, tid);       // Uf stays resident for all 8 children
    for (int k=0;k<8;k++){
        load_child_cvt_accum(xs, hs, child_h, m0, k, tid);
        __syncthreads();                   // tile (and Uf on k==0) visible to all warps
        ZERO_ACC(acc);
        gemm128(acc, xs, wb, g, r, wm, wn);
        #pragma unroll
        for (int mt=0;mt<4;mt++)
          #pragma unroll
          for (int nt=0;nt<4;nt++){
            int R0 = m0 + wm*64 + mt*16 + g;
            int C0 = wn*32 + nt*8 + 2*r;
            float2 c0 = *reinterpret_cast<const float2*>(child_c + ( R0   *8 + k)*128 + C0);
            float2 c1 = *reinterpret_cast<const float2*>(child_c + ((R0+8)*8 + k)*128 + C0);
            cacc[mt][nt][0] += sigf(aux[mt][nt][0] + acc[mt][nt][0]) * c0.x;
            cacc[mt][nt][1] += sigf(aux[mt][nt][1] + acc[mt][nt][1]) * c0.y;
            cacc[mt][nt][2] += sigf(aux[mt][nt][2] + acc[mt][nt][2]) * c1.x;
            cacc[mt][nt][3] += sigf(aux[mt][nt][3] + acc[mt][nt][3]) * c1.y;
          }
        __syncthreads();                   // before next k overwrites xs
    }

    // ---- phase 3: reload x, round h_sum to tf32 ------------------------
    load_cvt(xs, LDA, x + m0*128, 128, tid);
    #pragma unroll
    for (int i=0;i<16;i++){
        int e = tid + i*THREADS;
        int row = e>>5, c4=(e&31)*4;
        float4* hp = reinterpret_cast<float4*>(hs + row*LDA + c4);
        float4 v = *hp;
        v.x=tf32r(v.x); v.y=tf32r(v.y); v.z=tf32r(v.z); v.w=tf32r(v.w);
        *hp = v;
    }

    const float* Ws[3] = {Wu, Wi, Wo};
    const float* Us[3] = {Uu, Ui, Uo};
    const float* bs[3] = {bu, bi, bo};

    // ---- phase 4: gates u, i, o (in that order) ------------------------
    for (int gate=0; gate<3; gate++){
        load_cvt(wb, LDW, Ws[gate], 128, tid);
        __syncthreads();
        ZERO_ACC(acc);
        gemm128(acc, xs, wb, g, r, wm, wn);
        __syncthreads();
        load_cvt(wb, LDW, Us[gate], 128, tid);
        __syncthreads();
        gemm128(acc, hs, wb, g, r, wm, wn);
        __syncthreads();                   // before next gate's weight load

        const float* bp = bs[gate];
        #pragma unroll
        for (int mt=0;mt<4;mt++)
          #pragma unroll
          for (int nt=0;nt<4;nt++){
            int C0 = wn*32 + nt*8 + 2*r;
            float2 bv = *reinterpret_cast<const float2*>(bp + C0);
            float p0 = acc[mt][nt][0] + bv.x;
            float p1 = acc[mt][nt][1] + bv.y;
            float p2 = acc[mt][nt][2] + bv.x;
            float p3 = acc[mt][nt][3] + bv.y;
            if (gate == 0){                // u = tanh(...)
                aux[mt][nt][0] = tanhfast(p0);
                aux[mt][nt][1] = tanhfast(p1);
                aux[mt][nt][2] = tanhfast(p2);
                aux[mt][nt][3] = tanhfast(p3);
            } else if (gate == 1){         // cacc += sigmoid(i) * u
                cacc[mt][nt][0] += sigf(p0) * aux[mt][nt][0];
                cacc[mt][nt][1] += sigf(p1) * aux[mt][nt][1];
                cacc[mt][nt][2] += sigf(p2) * aux[mt][nt][2];
                cacc[mt][nt][3] += sigf(p3) * aux[mt][nt][3];
            } else {                       // o: finalize h and c, write out
                int R0 = m0 + wm*64 + mt*16 + g;
                float c0 = cacc[mt][nt][0], c1 = cacc[mt][nt][1];
                float c2 = cacc[mt][nt][2], c3 = cacc[mt][nt][3];
                float h0 = sigf(p0) * tanhfast(c0);
                float h1 = sigf(p1) * tanhfast(c1);
                float h2 = sigf(p2) * tanhfast(c2);
                float h3 = sigf(p3) * tanhfast(c3);
                float* outh = out;
                float* outc = out + (size_t)N*128;
                *reinterpret_cast<float2*>(outh +  R0   *128 + C0) = make_float2(h0,h1);
                *reinterpret_cast<float2*>(outh + (R0+8)*128 + C0) = make_float2(h2,h3);
                *reinterpret_cast<float2*>(outc +  R0   *128 + C0) = make_float2(c0,c1);
                *reinterpret_cast<float2*>(outc + (R0+8)*128 + C0) = make_float2(c2,c3);
            }
          }
    }
}

extern "C" void kernel_launch(void* const* d_in, const int* in_sizes, int n_in,
                              void* d_out, int out_size)
{
    const float* x       = (const float*)d_in[0];
    const float* child_h = (const float*)d_in[1];
    const float* child_c = (const float*)d_in[2];
    const float* Wi = (const float*)d_in[3];
    const float* bi = (const float*)d_in[4];
    const float* Ui = (const float*)d_in[5];
    const float* Wo = (const float*)d_in[6];
    const float* bo = (const float*)d_in[7];
    const float* Uo = (const float*)d_in[8];
    const float* Wu = (const float*)d_in[9];
    const float* bu = (const float*)d_in[10];
    const float* Uu = (const float*)d_in[11];
    const float* Wf = (const float*)d_in[12];
    const float* bf = (const float*)d_in[13];
    const float* Uf = (const float*)d_in[14];
    float* out = (float*)d_out;

    int N = in_sizes[0] / 128;
    int blocks = N / 128;

    cudaFuncSetAttribute(treelstm_kernel,
                         cudaFuncAttributeMaxDynamicSharedMemorySize, SMEM_BYTES);
    treelstm_kernel<<<blocks, THREADS, SMEM_BYTES>>>(
        x, child_h, child_c,
        Wi, bi, Ui, Wo, bo, Uo, Wu, bu, Uu, Wf, bf, Uf,
        out, N);
}

// round 3
// speedup vs baseline: 1.3000x; 1.3000x over previous
#include <cuda_runtime.h>
#include <cstdint>

#define LDA 132
#define THREADS 256
#define ROWS 64

// smem floats: xt(64*LDA) hs(64*LDA) bufA(64*LDA) bufB(64*LDA) wb(128*LDA)
// bufA+bufB are adjacent => also usable as a 128-row weight buffer wb2.
#define SMEM_FLOATS (64*LDA*4 + 128*LDA)
#define SMEM_BYTES  (SMEM_FLOATS*4)

__device__ __forceinline__ float tf32r(float v){
    uint32_t u; asm("cvt.rna.tf32.f32 %0, %1;" : "=r"(u) : "f"(v));
    return __uint_as_float(u);
}
__device__ __forceinline__ float sigf(float v){
    float t = __expf(-v);
    return __fdividef(1.0f, 1.0f + t);
}
__device__ __forceinline__ float tanhfast(float v){
    v = fminf(fmaxf(v, -15.0f), 15.0f);
    float t = __expf(-2.0f*v);
    return __fdividef(1.0f - t, 1.0f + t);
}

__device__ __forceinline__ void cpa16(uint32_t s, const float* g){
    asm volatile("cp.async.cg.shared.global [%0], [%1], 16;\n" :: "r"(s), "l"(g));
}
#define CP_COMMIT() asm volatile("cp.async.commit_group;\n" ::: "memory")
#define CP_WAIT(n)  asm volatile("cp.async.wait_group %0;\n" :: "n"(n) : "memory")

// async-copy a R x 128 fp32 tile (row stride rs in gmem) into smem with stride LDA
template<int R>
__device__ __forceinline__ void cpa_tile(float* dst, const float* __restrict__ src,
                                         int rs, int tid){
    uint32_t base = (uint32_t)__cvta_generic_to_shared(dst);
    #pragma unroll
    for (int i=0;i<R/8;i++){
        int e = tid + i*THREADS;
        int row = e >> 5;
        int c4  = (e & 31) * 4;
        cpa16(base + (uint32_t)(row*LDA + c4)*4u, src + row*rs + c4);
    }
}

// round a R x 128 tile to tf32 in place
template<int R>
__device__ __forceinline__ void cvt_tile(float* t, int tid){
    #pragma unroll
    for (int i=0;i<R/8;i++){
        int e = tid + i*THREADS;
        int row = e >> 5;
        int c4  = (e & 31) * 4;
        float4* p = reinterpret_cast<float4*>(t + row*LDA + c4);
        float4 v = *p;
        v.x=tf32r(v.x); v.y=tf32r(v.y); v.z=tf32r(v.z); v.w=tf32r(v.w);
        *p = v;
    }
}

// child tile: accumulate raw value into hs, round tile in place
__device__ __forceinline__ void cvt_child_accum(float* buf, float* hs, int tid){
    #pragma unroll
    for (int i=0;i<8;i++){
        int e = tid + i*THREADS;
        int row = e >> 5;
        int c4  = (e & 31) * 4;
        float4* p = reinterpret_cast<float4*>(buf + row*LDA + c4);
        float4 v = *p;
        float4* hp = reinterpret_cast<float4*>(hs + row*LDA + c4);
        float4 h = *hp;
        h.x += v.x; h.y += v.y; h.z += v.z; h.w += v.w;
        *hp = h;
        v.x=tf32r(v.x); v.y=tf32r(v.y); v.z=tf32r(v.z); v.w=tf32r(v.w);
        *p = v;
    }
}

__device__ __forceinline__ void mma8(float* c, const uint32_t* a, const uint32_t* b){
    asm volatile(
      "mma.sync.aligned.m16n8k8.row.col.f32.tf32.tf32.f32 "
      "{%0,%1,%2,%3},{%4,%5,%6,%7},{%8,%9},{%0,%1,%2,%3};\n"
      : "+f"(c[0]), "+f"(c[1]), "+f"(c[2]), "+f"(c[3])
      : "r"(a[0]), "r"(a[1]), "r"(a[2]), "r"(a[3]),
        "r"(b[0]), "r"(b[1]));
}

// 64x128x128 tf32 GEMM; 8 warps as 2(m) x 4(n); warp tile 32 x 32.
__device__ __forceinline__ void gemm64(float (&acc)[2][4][4],
                                       const float* __restrict__ As,
                                       const float* __restrict__ Bs,
                                       int g, int r, int wm, int wn)
{
    #pragma unroll 4
    for (int k8 = 0; k8 < 16; k8++){
        const int kk = k8*8;
        uint32_t a[2][4];
        #pragma unroll
        for (int mt=0; mt<2; mt++){
            const float* ap = As + (wm*32 + mt*16 + g)*LDA + kk + r;
            a[mt][0] = __float_as_uint(ap[0]);
            a[mt][1] = __float_as_uint(ap[8*LDA]);
            a[mt][2] = __float_as_uint(ap[4]);
            a[mt][3] = __float_as_uint(ap[8*LDA+4]);
        }
        uint32_t b[4][2];
        #pragma unroll
        for (int nt=0; nt<4; nt++){
            const float* bp = Bs + (kk + r)*LDA + wn*32 + nt*8 + g;
            b[nt][0] = __float_as_uint(bp[0]);
            b[nt][1] = __float_as_uint(bp[4*LDA]);
        }
        #pragma unroll
        for (int mt=0; mt<2; mt++)
          #pragma unroll
          for (int nt=0; nt<4; nt++)
            mma8(acc[mt][nt], a[mt], b[nt]);
    }
}

#define ZERO_ACC(A) { _Pragma("unroll") for(int _m=0;_m<2;_m++) _Pragma("unroll") for(int _n=0;_n<4;_n++) _Pragma("unroll") for(int _e=0;_e<4;_e++) (A)[_m][_n][_e]=0.0f; }

__global__ void __launch_bounds__(THREADS, 1)
treelstm_kernel(const float* __restrict__ x,
                const float* __restrict__ child_h,
                const float* __restrict__ child_c,
                const float* __restrict__ Wi, const float* __restrict__ bi, const float* __restrict__ Ui,
                const float* __restrict__ Wo, const float* __restrict__ bo, const float* __restrict__ Uo,
                const float* __restrict__ Wu, const float* __restrict__ bu, const float* __restrict__ Uu,
                const float* __restrict__ Wf, const float* __restrict__ bf, const float* __restrict__ Uf,
                float* __restrict__ out, int N)
{
    extern __shared__ float smem[];
    float* xt   = smem;              // 64xLDA : x tile (tf32), resident entire kernel
    float* hs   = xt   + 64*LDA;     // 64xLDA : h_sum
    float* bufA = hs   + 64*LDA;     // 64xLDA : child ping  \  wb2 = bufA as 128-row
    float* bufB = bufA + 64*LDA;     // 64xLDA : child pong  /
    float* wb   = bufB + 64*LDA;     // 128xLDA : weight buffer
    float* wb2  = bufA;              // 128-row alias used in gate phase

    const int tid  = threadIdx.x;
    const int lane = tid & 31;
    const int g    = lane >> 2;
    const int r    = lane & 3;
    const int wid  = tid >> 5;
    const int wm   = wid & 1;
    const int wn   = wid >> 1;
    const int m0   = blockIdx.x * ROWS;

    float acc [2][4][4];
    float cacc[2][4][4];
    float aux [2][4][4];   // xf during child loop, then u

    // ---- prologue: async loads of x, Wf, ch0, ch1 ----------------------
    cpa_tile<64 >(xt, x + (size_t)m0*128, 128, tid);
    cpa_tile<128>(wb, Wf, 128, tid);
    CP_COMMIT();                                   // grp: x+Wf
    cpa_tile<64>(bufA, child_h + ((size_t)m0*8 + 0)*128, 8*128, tid);
    CP_COMMIT();                                   // grp: ch0
    cpa_tile<64>(bufB, child_h + ((size_t)m0*8 + 1)*128, 8*128, tid);
    CP_COMMIT();                                   // grp: ch1

    // zero h_sum (thread-private element ownership, no barrier needed)
    #pragma unroll
    for (int i=0;i<8;i++){
        int e = tid + i*THREADS;
        int row = e>>5, c4=(e&31)*4;
        *reinterpret_cast<float4*>(hs + row*LDA + c4) = make_float4(0.f,0.f,0.f,0.f);
    }

    CP_WAIT(2); __syncthreads();                   // x + Wf arrived
    cvt_tile<64>(xt, tid);
    cvt_tile<128>(wb, tid);
    __syncthreads();

    // ---- phase 1: xf = x @ Wf + bf -------------------------------------
    ZERO_ACC(acc);
    gemm64(acc, xt, wb, g, r, wm, wn);
    __syncthreads();                               // wb free for Uf
    cpa_tile<128>(wb, Uf, 128, tid);
    CP_COMMIT();                                   // grp: Uf

    #pragma unroll
    for (int mt=0;mt<2;mt++)
      #pragma unroll
      for (int nt=0;nt<4;nt++){
        int C0 = wn*32 + nt*8 + 2*r;
        float2 bv = *reinterpret_cast<const float2*>(bf + C0);
        aux[mt][nt][0] = acc[mt][nt][0] + bv.x;
        aux[mt][nt][1] = acc[mt][nt][1] + bv.y;
        aux[mt][nt][2] = acc[mt][nt][2] + bv.x;
        aux[mt][nt][3] = acc[mt][nt][3] + bv.y;
        cacc[mt][nt][0]=0.f; cacc[mt][nt][1]=0.f;
        cacc[mt][nt][2]=0.f; cacc[mt][nt][3]=0.f;
      }

    // ---- phase 2: children -------------------------------------------
    for (int k=0;k<8;k++){
        float* buf = (k&1) ? bufB : bufA;
        CP_WAIT(0);                                // ch_k (+Uf when k==0)
        __syncthreads();
        if (k==0) cvt_tile<128>(wb, tid);          // round Uf once
        cvt_child_accum(buf, hs, tid);             // hs += raw, buf -> tf32
        // prefetch child_c[k] (consumed after gemm)
        float2 cc[2][4][2];
        #pragma unroll
        for (int mt=0;mt<2;mt++)
          #pragma unroll
          for (int nt=0;nt<4;nt++){
            int R0 = m0 + wm*32 + mt*16 + g;
            int C0 = wn*32 + nt*8 + 2*r;
            cc[mt][nt][0] = *reinterpret_cast<const float2*>(child_c + ((size_t)R0*8 + k)*128 + C0);
            cc[mt][nt][1] = *reinterpret_cast<const float2*>(child_c + ((size_t)(R0+8)*8 + k)*128 + C0);
          }
        // issue next child load into the buffer freed by gemm k-1
        if (k>=1 && k<7){
            float* nbuf = (k&1) ? bufA : bufB;
            cpa_tile<64>(nbuf, child_h + ((size_t)m0*8 + (k+1))*128, 8*128, tid);
            CP_COMMIT();
        }
        __syncthreads();                           // converted tile (+Uf) visible
        ZERO_ACC(acc);
        gemm64(acc, buf, wb, g, r, wm, wn);
        #pragma unroll
        for (int mt=0;mt<2;mt++)
          #pragma unroll
          for (int nt=0;nt<4;nt++){
            cacc[mt][nt][0] += sigf(aux[mt][nt][0] + acc[mt][nt][0]) * cc[mt][nt][0].x;
            cacc[mt][nt][1] += sigf(aux[mt][nt][1] + acc[mt][nt][1]) * cc[mt][nt][0].y;
            cacc[mt][nt][2] += sigf(aux[mt][nt][2] + acc[mt][nt][2]) * cc[mt][nt][1].x;
            cacc[mt][nt][3] += sigf(aux[mt][nt][3] + acc[mt][nt][3]) * cc[mt][nt][1].y;
          }
    }

    __syncthreads();                               // bufs + wb free
    // ---- phase 3: gates u, i, o with ping-pong weight prefetch --------
    cpa_tile<128>(wb2, Wu, 128, tid); CP_COMMIT();
    cpa_tile<128>(wb , Uu, 128, tid); CP_COMMIT();
    cvt_tile<64>(hs, tid);                         // round h_sum (own elements)

    const float* Ws[3] = {Wu, Wi, Wo};
    const float* Us[3] = {Uu, Ui, Uo};
    const float* bs[3] = {bu, bi, bo};

    for (int gate=0; gate<3; gate++){
        CP_WAIT(1);                                // W_gate arrived
        __syncthreads();
        cvt_tile<128>(wb2, tid);
        __syncthreads();
        ZERO_ACC(acc);
        gemm64(acc, xt, wb2, g, r, wm, wn);
        __syncthreads();                           // wb2 free
        if (gate<2){ cpa_tile<128>(wb2, Ws[gate+1], 128, tid); CP_COMMIT(); }

        if (gate<2) { CP_WAIT(1); } else { CP_WAIT(0); }   // U_gate arrived
        __syncthreads();
        cvt_tile<128>(wb, tid);
        __syncthreads();
        gemm64(acc, hs, wb, g, r, wm, wn);
        __syncthreads();                           // wb free
        if (gate<2){ cpa_tile<128>(wb, Us[gate+1], 128, tid); CP_COMMIT(); }

        const float* bp = bs[gate];
        #pragma unroll
        for (int mt=0;mt<2;mt++)
          #pragma unroll
          for (int nt=0;nt<4;nt++){
            int C0 = wn*32 + nt*8 + 2*r;
            float2 bv = *reinterpret_cast<const float2*>(bp + C0);
            float p0 = acc[mt][nt][0] + bv.x;
            float p1 = acc[mt][nt][1] + bv.y;
            float p2 = acc[mt][nt][2] + bv.x;
            float p3 = acc[mt][nt][3] + bv.y;
            if (gate == 0){
                aux[mt][nt][0] = tanhfast(p0);
                aux[mt][nt][1] = tanhfast(p1);
                aux[mt][nt][2] = tanhfast(p2);
                aux[mt][nt][3] = tanhfast(p3);
            } else if (gate == 1){
                cacc[mt][nt][0] += sigf(p0) * aux[mt][nt][0];
                cacc[mt][nt][1] += sigf(p1) * aux[mt][nt][1];
                cacc[mt][nt][2] += sigf(p2) * aux[mt][nt][2];
                cacc[mt][nt][3] += sigf(p3) * aux[mt][nt][3];
            } else {
                int R0 = m0 + wm*32 + mt*16 + g;
                float c0 = cacc[mt][nt][0], c1 = cacc[mt][nt][1];
                float c2 = cacc[mt][nt][2], c3 = cacc[mt][nt][3];
                float h0 = sigf(p0) * tanhfast(c0);
                float h1 = sigf(p1) * tanhfast(c1);
                float h2 = sigf(p2) * tanhfast(c2);
                float h3 = sigf(p3) * tanhfast(c3);
                float* outh = out;
                float* outc = out + (size_t)N*128;
                *reinterpret_cast<float2*>(outh + (size_t) R0   *128 + C0) = make_float2(h0,h1);
                *reinterpret_cast<float2*>(outh + (size_t)(R0+8)*128 + C0) = make_float2(h2,h3);
                *reinterpret_cast<float2*>(outc + (size_t) R0   *128 + C0) = make_float2(c0,c1);
                *reinterpret_cast<float2*>(outc + (size_t)(R0+8)*128 + C0) = make_float2(c2,c3);
            }
          }
    }
}

extern "C" void kernel_launch(void* const* d_in, const int* in_sizes, int n_in,
                              void* d_out, int out_size)
{
    const float* x       = (const float*)d_in[0];
    const float* child_h = (const float*)d_in[1];
    const float* child_c = (const float*)d_in[2];
    const float* Wi = (const float*)d_in[3];
    const float* bi = (const float*)d_in[4];
    const float* Ui = (const float*)d_in[5];
    const float* Wo = (const float*)d_in[6];
    const float* bo = (const float*)d_in[7];
    const float* Uo = (const float*)d_in[8];
    const float* Wu = (const float*)d_in[9];
    const float* bu = (const float*)d_in[10];
    const float* Uu = (const float*)d_in[11];
    const float* Wf = (const float*)d_in[12];
    const float* bf = (const float*)d_in[13];
    const float* Uf = (const float*)d_in[14];
    float* out = (float*)d_out;

    int N = in_sizes[0] / 128;
    int blocks = N / ROWS;

    cudaFuncSetAttribute(treelstm_kernel,
                         cudaFuncAttributeMaxDynamicSharedMemorySize, SMEM_BYTES);
    treelstm_kernel<<<blocks, THREADS, SMEM_BYTES>>>(
        x, child_h, child_c,
        Wi, bi, Ui, Wo, bo, Uo, Wu, bu, Uu, Wf, bf, Uf,
        out, N);
}

// round 4
// speedup vs baseline: 1.7318x; 1.3322x over previous
#include <cuda_runtime.h>
#include <cstdint>

#define LDA 132
#define THREADS 256
#define ROWS 64

// smem: hs(64) | B(64: x/cc/x) | CD(128: Wf/Uf/U-gates) | EF(128: child ping+pong / W-gates)
#define SMEM_FLOATS (384*LDA)
#define SMEM_BYTES  (SMEM_FLOATS*4)

__device__ float wbuf[8][128*LDA];   // pre-transposed, pre-rounded tf32 weights [n][k]

__device__ __forceinline__ float tf32r(float v){
    uint32_t u; asm("cvt.rna.tf32.f32 %0, %1;" : "=r"(u) : "f"(v));
    return __uint_as_float(u);
}
__device__ __forceinline__ float sigf(float v){
    float t = __expf(-v);
    return __fdividef(1.0f, 1.0f + t);
}
__device__ __forceinline__ float tanhfast(float v){
    v = fminf(fmaxf(v, -15.0f), 15.0f);
    float t = __expf(-2.0f*v);
    return __fdividef(1.0f - t, 1.0f + t);
}

__device__ __forceinline__ void cpa16(uint32_t s, const float* g){
    asm volatile("cp.async.cg.shared.global [%0], [%1], 16;\n" :: "r"(s), "l"(g));
}
#define CP_COMMIT() asm volatile("cp.async.commit_group;\n" ::: "memory")
#define CP_WAIT(n)  asm volatile("cp.async.wait_group %0;\n" :: "n"(n) : "memory")

template<int R>
__device__ __forceinline__ void cpa_tile(float* dst, const float* __restrict__ src,
                                         int rs, int tid){
    uint32_t base = (uint32_t)__cvta_generic_to_shared(dst);
    #pragma unroll
    for (int i=0;i<R/8;i++){
        int e = tid + i*THREADS;
        int row = e >> 5;
        int c4  = (e & 31) * 4;
        cpa16(base + (uint32_t)(row*LDA + c4)*4u, src + (size_t)row*rs + c4);
    }
}

template<int R>
__device__ __forceinline__ void cvt_tile(float* t, int tid){
    #pragma unroll
    for (int i=0;i<R/8;i++){
        int e = tid + i*THREADS;
        int row = e >> 5;
        int c4  = (e & 31) * 4;
        float4* p = reinterpret_cast<float4*>(t + row*LDA + c4);
        float4 v = *p;
        v.x=tf32r(v.x); v.y=tf32r(v.y); v.z=tf32r(v.z); v.w=tf32r(v.w);
        *p = v;
    }
}

__device__ __forceinline__ void cvt_child_accum(float* buf, float* hs, int tid){
    #pragma unroll
    for (int i=0;i<8;i++){
        int e = tid + i*THREADS;
        int row = e >> 5;
        int c4  = (e & 31) * 4;
        float4* p = reinterpret_cast<float4*>(buf + row*LDA + c4);
        float4 v = *p;
        float4* hp = reinterpret_cast<float4*>(hs + row*LDA + c4);
        float4 h = *hp;
        h.x += v.x; h.y += v.y; h.z += v.z; h.w += v.w;
        *hp = h;
        v.x=tf32r(v.x); v.y=tf32r(v.y); v.z=tf32r(v.z); v.w=tf32r(v.w);
        *p = v;
    }
}

__device__ __forceinline__ void mma8(float* c, const uint32_t* a, const uint32_t* b){
    asm volatile(
      "mma.sync.aligned.m16n8k8.row.col.f32.tf32.tf32.f32 "
      "{%0,%1,%2,%3},{%4,%5,%6,%7},{%8,%9},{%0,%1,%2,%3};\n"
      : "+f"(c[0]), "+f"(c[1]), "+f"(c[2]), "+f"(c[3])
      : "r"(a[0]), "r"(a[1]), "r"(a[2]), "r"(a[3]),
        "r"(b[0]), "r"(b[1]));
}

__device__ __forceinline__ void ldsm4(uint32_t* d, uint32_t saddr){
    asm volatile("ldmatrix.sync.aligned.m8n8.x4.shared.b16 {%0,%1,%2,%3}, [%4];\n"
      : "=r"(d[0]),"=r"(d[1]),"=r"(d[2]),"=r"(d[3]) : "r"(saddr));
}

// 64x128x128 tf32 GEMM; A row-major [m][k], B transposed [n][k]; all frags via ldmatrix.
__device__ __forceinline__ void gemm64(float (&acc)[2][4][4],
                                       const float* __restrict__ As,
                                       const float* __restrict__ Bs,
                                       int lane, int wm, int wn)
{
    uint32_t abase = (uint32_t)__cvta_generic_to_shared(As);
    uint32_t bbase = (uint32_t)__cvta_generic_to_shared(Bs);
    // A: matrices {rows 0-7,kk},{rows 8-15,kk},{rows 0-7,kk+4},{rows 8-15,kk+4}
    int aRow = wm*32 + (lane&7) + ((lane>>3)&1)*8;
    int aCol = ((lane>>4)&1)*4;
    uint32_t aoff = abase + (uint32_t)(aRow*LDA + aCol)*4u;
    // B: matrices {n 0-7,kk},{n 0-7,kk+4},{n 8-15,kk},{n 8-15,kk+4}
    int bRow = wn*32 + (lane&7) + ((lane>>4)&1)*8;
    int bCol = ((lane>>3)&1)*4;
    uint32_t boff = bbase + (uint32_t)(bRow*LDA + bCol)*4u;

    #pragma unroll
    for (int k8=0;k8<16;k8++){
        uint32_t a[2][4], b[2][4];
        ldsm4(a[0], aoff + k8*32u);
        ldsm4(a[1], aoff + 16u*LDA*4u + k8*32u);
        ldsm4(b[0], boff + k8*32u);                 // nt 0,1
        ldsm4(b[1], boff + 16u*LDA*4u + k8*32u);    // nt 2,3
        #pragma unroll
        for (int mt=0; mt<2; mt++){
            mma8(acc[mt][0], a[mt], &b[0][0]);
            mma8(acc[mt][1], a[mt], &b[0][2]);
            mma8(acc[mt][2], a[mt], &b[1][0]);
            mma8(acc[mt][3], a[mt], &b[1][2]);
        }
    }
}

#define ZERO_ACC(A) { _Pragma("unroll") for(int _m=0;_m<2;_m++) _Pragma("unroll") for(int _n=0;_n<4;_n++) _Pragma("unroll") for(int _e=0;_e<4;_e++) (A)[_m][_n][_e]=0.0f; }

// ---- prep: transpose + tf32-round all 8 weight matrices into wbuf ------
__global__ void prep_weights(const float* __restrict__ Wf, const float* __restrict__ Uf,
                             const float* __restrict__ Wu, const float* __restrict__ Uu,
                             const float* __restrict__ Wi, const float* __restrict__ Ui,
                             const float* __restrict__ Wo, const float* __restrict__ Uo)
{
    const float* srcs[8] = {Wf,Uf,Wu,Uu,Wi,Ui,Wo,Uo};
    const float* s = srcs[blockIdx.x];
    float* d = wbuf[blockIdx.x];
    for (int i = threadIdx.x; i < 128*128; i += blockDim.x){
        int n = i >> 7, k = i & 127;
        d[n*LDA + k] = tf32r(s[k*128 + n]);      // [n][k], tf32-rounded
    }
}

__global__ void __launch_bounds__(THREADS, 1)
treelstm_kernel(const float* __restrict__ x,
                const float* __restrict__ child_h,
                const float* __restrict__ child_c,
                const float* __restrict__ bi, const float* __restrict__ bo,
                const float* __restrict__ bu, const float* __restrict__ bf,
                float* __restrict__ out, int N)
{
    extern __shared__ float smem[];
    float* hsA  = smem;               // 64 rows : h_sum (fp32 -> tf32)
    float* Bt   = smem + 64*LDA;      // 64 rows : x tile / child_c / x tile
    float* CDw  = smem + 128*LDA;     // 128 rows: Wf / Uf / U-gates
    float* EFw  = smem + 256*LDA;     // 128 rows: child ping+pong / W-gates
    float* bufA = EFw;
    float* bufB = EFw + 64*LDA;

    const int tid  = threadIdx.x;
    const int lane = tid & 31;
    const int g    = lane >> 2;
    const int r    = lane & 3;
    const int wid  = tid >> 5;
    const int wm   = wid & 1;
    const int wn   = wid >> 1;
    const int m0   = blockIdx.x * ROWS;

    float acc [2][4][4];
    float cacc[2][4][4];
    float aux [2][4][4];

    // ---- prologue ------------------------------------------------------
    cpa_tile<64 >(Bt,  x + (size_t)m0*128, 128, tid);
    cpa_tile<128>(CDw, wbuf[0], LDA, tid);                 // Wf (ready-to-use)
    CP_COMMIT();                                           // G1
    cpa_tile<64>(bufA, child_h + ((size_t)m0*8 + 0)*128, 8*128, tid);
    CP_COMMIT();                                           // G2
    cpa_tile<64>(bufB, child_h + ((size_t)m0*8 + 1)*128, 8*128, tid);
    CP_COMMIT();                                           // G3

    #pragma unroll
    for (int i=0;i<8;i++){
        int e = tid + i*THREADS;
        int row = e>>5, c4=(e&31)*4;
        *reinterpret_cast<float4*>(hsA + row*LDA + c4) = make_float4(0.f,0.f,0.f,0.f);
    }

    CP_WAIT(2); __syncthreads();                           // x + Wf
    cvt_tile<64>(Bt, tid);
    __syncthreads();

    // ---- phase 1: xf = x @ Wf + bf -------------------------------------
    ZERO_ACC(acc);
    gemm64(acc, Bt, CDw, lane, wm, wn);
    __syncthreads();                                       // Bt, CDw free
    cpa_tile<128>(CDw, wbuf[1], LDA, tid);                 // Uf
    CP_COMMIT();                                           // G4

    #pragma unroll
    for (int mt=0;mt<2;mt++)
      #pragma unroll
      for (int nt=0;nt<4;nt++){
        int C0 = wn*32 + nt*8 + 2*r;
        float2 bv = *reinterpret_cast<const float2*>(bf + C0);
        aux[mt][nt][0] = acc[mt][nt][0] + bv.x;
        aux[mt][nt][1] = acc[mt][nt][1] + bv.y;
        aux[mt][nt][2] = acc[mt][nt][2] + bv.x;
        aux[mt][nt][3] = acc[mt][nt][3] + bv.y;
        cacc[mt][nt][0]=0.f; cacc[mt][nt][1]=0.f;
        cacc[mt][nt][2]=0.f; cacc[mt][nt][3]=0.f;
      }

    // ---- phase 2: children ---------------------------------------------
    for (int k=0;k<8;k++){
        float* buf = (k&1) ? bufB : bufA;
        CP_WAIT(0);                                        // ch_k (+Uf at k=0)
        __syncthreads();                                   // (a) prev epilogue done
        cvt_child_accum(buf, hsA, tid);
        // cc_k into Bt (free since (a)); then next child
        cpa_tile<64>(Bt, child_c + ((size_t)m0*8 + k)*128, 8*128, tid);
        CP_COMMIT();
        if (k<7){
            float* nbuf = (k&1) ? bufA : bufB;
            cpa_tile<64>(nbuf, child_h + ((size_t)m0*8 + (k+1))*128, 8*128, tid);
            CP_COMMIT();
        }
        __syncthreads();                                   // (b) cvt visible
        ZERO_ACC(acc);
        gemm64(acc, buf, CDw, lane, wm, wn);
        if (k<7) { CP_WAIT(1); } else { CP_WAIT(0); }      // cc_k done
        __syncthreads();                                   // (c) cc visible
        #pragma unroll
        for (int mt=0;mt<2;mt++)
          #pragma unroll
          for (int nt=0;nt<4;nt++){
            int Rr = wm*32 + mt*16 + g;
            int C0 = wn*32 + nt*8 + 2*r;
            float2 c0 = *reinterpret_cast<const float2*>(Bt +  Rr   *LDA + C0);
            float2 c1 = *reinterpret_cast<const float2*>(Bt + (Rr+8)*LDA + C0);
            cacc[mt][nt][0] += sigf(aux[mt][nt][0] + acc[mt][nt][0]) * c0.x;
            cacc[mt][nt][1] += sigf(aux[mt][nt][1] + acc[mt][nt][1]) * c0.y;
            cacc[mt][nt][2] += sigf(aux[mt][nt][2] + acc[mt][nt][2]) * c1.x;
            cacc[mt][nt][3] += sigf(aux[mt][nt][3] + acc[mt][nt][3]) * c1.y;
          }
    }

    __syncthreads();                                       // all bufs free
    cvt_tile<64>(hsA, tid);                                // round h_sum (own elems)
    cpa_tile<64 >(Bt,  x + (size_t)m0*128, 128, tid);      // x reload
    cpa_tile<128>(EFw, wbuf[2], LDA, tid);                 // Wu
    CP_COMMIT();                                           // G: x+Wu
    cpa_tile<128>(CDw, wbuf[3], LDA, tid);                 // Uu
    CP_COMMIT();                                           // G: Uu

    const float* bs[3] = {bu, bi, bo};

    // ---- phase 3: gates u, i, o ----------------------------------------
    for (int gate=0; gate<3; gate++){
        CP_WAIT(1); __syncthreads();                       // W_gate (+x at gate0)
        if (gate==0){ cvt_tile<64>(Bt, tid); __syncthreads(); }
        ZERO_ACC(acc);
        gemm64(acc, Bt, EFw, lane, wm, wn);
        __syncthreads();                                   // EFw free
        if (gate<2){ cpa_tile<128>(EFw, wbuf[4 + 2*gate], LDA, tid); CP_COMMIT(); }

        if (gate<2) { CP_WAIT(1); } else { CP_WAIT(0); }   // U_gate
        __syncthreads();
        gemm64(acc, hsA, CDw, lane, wm, wn);
        __syncthreads();                                   // CDw free
        if (gate<2){ cpa_tile<128>(CDw, wbuf[5 + 2*gate], LDA, tid); CP_COMMIT(); }

        const float* bp = bs[gate];
        #pragma unroll
        for (int mt=0;mt<2;mt++)
          #pragma unroll
          for (int nt=0;nt<4;nt++){
            int C0 = wn*32 + nt*8 + 2*r;
            float2 bv = *reinterpret_cast<const float2*>(bp + C0);
            float p0 = acc[mt][nt][0] + bv.x;
            float p1 = acc[mt][nt][1] + bv.y;
            float p2 = acc[mt][nt][2] + bv.x;
            float p3 = acc[mt][nt][3] + bv.y;
            if (gate == 0){
                aux[mt][nt][0] = tanhfast(p0);
                aux[mt][nt][1] = tanhfast(p1);
                aux[mt][nt][2] = tanhfast(p2);
                aux[mt][nt][3] = tanhfast(p3);
            } else if (gate == 1){
                cacc[mt][nt][0] += sigf(p0) * aux[mt][nt][0];
                cacc[mt][nt][1] += sigf(p1) * aux[mt][nt][1];
                cacc[mt][nt][2] += sigf(p2) * aux[mt][nt][2];
                cacc[mt][nt][3] += sigf(p3) * aux[mt][nt][3];
            } else {
                int R0 = m0 + wm*32 + mt*16 + g;
                float c0 = cacc[mt][nt][0], c1 = cacc[mt][nt][1];
                float c2 = cacc[mt][nt][2], c3 = cacc[mt][nt][3];
                float h0 = sigf(p0) * tanhfast(c0);
                float h1 = sigf(p1) * tanhfast(c1);
                float h2 = sigf(p2) * tanhfast(c2);
                float h3 = sigf(p3) * tanhfast(c3);
                float* outh = out;
                float* outc = out + (size_t)N*128;
                *reinterpret_cast<float2*>(outh + (size_t) R0   *128 + C0) = make_float2(h0,h1);
                *reinterpret_cast<float2*>(outh + (size_t)(R0+8)*128 + C0) = make_float2(h2,h3);
                *reinterpret_cast<float2*>(outc + (size_t) R0   *128 + C0) = make_float2(c0,c1);
                *reinterpret_cast<float2*>(outc + (size_t)(R0+8)*128 + C0) = make_float2(c2,c3);
            }
          }
    }
}

extern "C" void kernel_launch(void* const* d_in, const int* in_sizes, int n_in,
                              void* d_out, int out_size)
{
    const float* x       = (const float*)d_in[0];
    const float* child_h = (const float*)d_in[1];
    const float* child_c = (const float*)d_in[2];
    const float* Wi = (const float*)d_in[3];
    const float* bi = (const float*)d_in[4];
    const float* Ui = (const float*)d_in[5];
    const float* Wo = (const float*)d_in[6];
    const float* bo = (const float*)d_in[7];
    const float* Uo = (const float*)d_in[8];
    const float* Wu = (const float*)d_in[9];
    const float* bu = (const float*)d_in[10];
    const float* Uu = (const float*)d_in[11];
    const float* Wf = (const float*)d_in[12];
    const float* bf = (const float*)d_in[13];
    const float* Uf = (const float*)d_in[14];
    float* out = (float*)d_out;

    int N = in_sizes[0] / 128;
    int blocks = N / ROWS;

    prep_weights<<<8, 256>>>(Wf, Uf, Wu, Uu, Wi, Ui, Wo, Uo);

    cudaFuncSetAttribute(treelstm_kernel,
                         cudaFuncAttributeMaxDynamicSharedMemorySize, SMEM_BYTES);
    treelstm_kernel<<<blocks, THREADS, SMEM_BYTES>>>(
        x, child_h, child_c, bi, bo, bu, bf, out, N);
}